// round 17
// baseline (speedup 1.0000x reference)
#include <cuda_runtime.h>
#include <cuda_bf16.h>
#include <cstdint>

#define B_ 4
#define S_ 4096
#define D_ 512
#define M1 (B_*S_)   // 16384

// ---------------- scratch (device globals: the sanctioned no-alloc path) ----
__device__ __nv_bfloat16 g_Xh [M1*D_];               // bf16 xs
__device__ __nv_bfloat16 g_Wkh[D_*D_];               // bf16 Wk
__device__ __nv_bfloat16 g_Wqh[D_*D_];               // bf16 Wq
__device__ __nv_bfloat16 g_Kh [B_*S_*D_];            // bf16 K
__device__ __nv_bfloat16 g_Qh [B_*S_*D_];            // bf16 Q
__device__ float         g_VL [B_*S_*D_];
__device__ __nv_bfloat16 g_E  [(size_t)B_*S_*S_];    // E[b][s][e] = exp(qk/512)
__device__ float         g_part[B_*32*S_];           // per-m-tile column sums
__device__ float         g_Linv[B_*S_];
__device__ float         g_r  [B_*S_];
__device__ float         g_WcP[2*D_*D_];             // split-K partials
__device__ float         g_Wc [D_*D_];
__device__ float         g_bc [D_];

// ---------------- helpers ---------------------------------------------------
__device__ __forceinline__ uint32_t f2tf(float x){
    uint32_t r; asm("cvt.rna.tf32.f32 %0, %1;" : "=r"(r) : "f"(x)); return r;
}
__device__ __forceinline__ void mma_tf(float c[4], const uint32_t a[4], const uint32_t b[2]){
    asm volatile(
        "mma.sync.aligned.m16n8k8.row.col.f32.tf32.tf32.f32 "
        "{%0,%1,%2,%3}, {%4,%5,%6,%7}, {%8,%9}, {%0,%1,%2,%3};"
        : "+f"(c[0]), "+f"(c[1]), "+f"(c[2]), "+f"(c[3])
        : "r"(a[0]), "r"(a[1]), "r"(a[2]), "r"(a[3]), "r"(b[0]), "r"(b[1]));
}
__device__ __forceinline__ void mma_bf(float c[4], const uint32_t a[4], const uint32_t b[2]){
    asm volatile(
        "mma.sync.aligned.m16n8k16.row.col.f32.bf16.bf16.f32 "
        "{%0,%1,%2,%3}, {%4,%5,%6,%7}, {%8,%9}, {%0,%1,%2,%3};"
        : "+f"(c[0]), "+f"(c[1]), "+f"(c[2]), "+f"(c[3])
        : "r"(a[0]), "r"(a[1]), "r"(a[2]), "r"(a[3]), "r"(b[0]), "r"(b[1]));
}

// ---------------- float -> bf16 cast (8 elems/thread) ------------------------
__global__ void cvt_bf16(const float4* __restrict__ src, uint4* __restrict__ dst){
    int i = blockIdx.x*256 + threadIdx.x;
    float4 a = src[2*i], b = src[2*i+1];
    __nv_bfloat162 p0 = __floats2bfloat162_rn(a.x, a.y);
    __nv_bfloat162 p1 = __floats2bfloat162_rn(a.z, a.w);
    __nv_bfloat162 p2 = __floats2bfloat162_rn(b.x, b.y);
    __nv_bfloat162 p3 = __floats2bfloat162_rn(b.z, b.w);
    uint4 q;
    q.x = *(uint32_t*)&p0; q.y = *(uint32_t*)&p1;
    q.z = *(uint32_t*)&p2; q.w = *(uint32_t*)&p3;
    dst[i] = q;
}

// ---------------- Wc = Wl @ Wv: split-K x2, reg-prefetched -------------------
__global__ void __launch_bounds__(256)
wc_gemm(const float* __restrict__ Wl, const float* __restrict__ Wv,
        float* __restrict__ WcP){
    __shared__ float sL[16][65];
    __shared__ float sV[16][65];
    const int bj = blockIdx.y*64, bi = blockIdx.x*64;
    const int z  = blockIdx.z;
    const int kbase = z*256;
    const int tx = threadIdx.x & 15, ty = threadIdx.x >> 4;

    float acc[4][4];
    #pragma unroll
    for (int m = 0; m < 4; m++)
        #pragma unroll
        for (int n = 0; n < 4; n++) acc[m][n] = 0.f;

    int rL[4], cL[4], rV[4], cV[4];
    #pragma unroll
    for (int p = 0; p < 4; p++){
        int idx = threadIdx.x + p*256;
        rL[p] = idx >> 4; cL[p] = idx & 15;
        rV[p] = idx >> 6; cV[p] = idx & 63;
    }

    float ra[4], rb[4];
    #pragma unroll
    for (int p = 0; p < 4; p++){
        ra[p] = Wl[(bj + rL[p])*D_ + kbase + cL[p]];
        rb[p] = Wv[(kbase + rV[p])*D_ + bi + cV[p]];
    }

    for (int it = 0; it < 16; it++){
        #pragma unroll
        for (int p = 0; p < 4; p++){
            sL[cL[p]][rL[p]] = ra[p];
            sV[rV[p]][cV[p]] = rb[p];
        }
        __syncthreads();
        if (it < 15){
            int k0 = kbase + (it + 1)*16;
            #pragma unroll
            for (int p = 0; p < 4; p++){
                ra[p] = Wl[(bj + rL[p])*D_ + k0 + cL[p]];
                rb[p] = Wv[(k0 + rV[p])*D_ + bi + cV[p]];
            }
        }
        #pragma unroll
        for (int k = 0; k < 16; k++){
            float a[4], b[4];
            #pragma unroll
            for (int m = 0; m < 4; m++) a[m] = sL[k][ty*4 + m];
            #pragma unroll
            for (int n = 0; n < 4; n++) b[n] = sV[k][tx*4 + n];
            #pragma unroll
            for (int m = 0; m < 4; m++)
                #pragma unroll
                for (int n = 0; n < 4; n++) acc[m][n] += a[m]*b[n];
        }
        __syncthreads();
    }
    #pragma unroll
    for (int m = 0; m < 4; m++)
        #pragma unroll
        for (int n = 0; n < 4; n++)
            WcP[(size_t)z*D_*D_ + (bj + ty*4 + m)*D_ + bi + tx*4 + n] = acc[m][n];
}

__global__ void wc_reduce(const float4* __restrict__ P, float4* __restrict__ Wc){
    int i = blockIdx.x*256 + threadIdx.x;
    float4 a = P[i], b = P[i + D_*D_/4];
    Wc[i] = make_float4(a.x+b.x, a.y+b.y, a.z+b.z, a.w+b.w);
}

// ---------------- bc = Wl @ bv ----------------------------------------------
__global__ void bc_kernel(const float* __restrict__ Wl, const float* __restrict__ bv,
                          float* __restrict__ bc){
    int j = blockIdx.x;
    __shared__ float red[128];
    float a = 0.f;
    for (int k = threadIdx.x; k < D_; k += 128) a += Wl[j*D_ + k]*bv[k];
    red[threadIdx.x] = a; __syncthreads();
    for (int s = 64; s > 0; s >>= 1){
        if (threadIdx.x < s) red[threadIdx.x] += red[threadIdx.x + s];
        __syncthreads();
    }
    if (threadIdx.x == 0) bc[j] = red[0];
}

// ---------------- tf32 mma GEMM (VL path): Cf = A @ B^T + bias --------------
#define BMT 128
#define BNT 128
#define LDT 36   // u32 row pitch with +4 pad: conflict-free LDS/STS

__global__ void __launch_bounds__(256, 2)
gemm_tf32(const float* __restrict__ Ag, const float* __restrict__ Bg,
          const float* __restrict__ bias, float* __restrict__ Cf,
          int M, int N, int K)
{
    __shared__ __align__(16) uint32_t sA[BMT*LDT];
    __shared__ __align__(16) uint32_t sB[BNT*LDT];

    const int tid  = threadIdx.x;
    const int bm = blockIdx.y*BMT, bn = blockIdx.x*BNT;
    const int lane = tid & 31, warp = tid >> 5;
    const int wm = (warp & 1)*64, wn = (warp >> 1)*32;
    const int g = lane >> 2, t = lane & 3;
    const int lrow = tid >> 3, lcol = (tid & 7)*4;

    float acc[4][4][4];
    #pragma unroll
    for (int i = 0; i < 4; i++)
        #pragma unroll
        for (int j = 0; j < 4; j++)
            #pragma unroll
            for (int c = 0; c < 4; c++) acc[i][j][c] = 0.f;

    float4 pa[4];
    #pragma unroll
    for (int p = 0; p < 4; p++)
        pa[p] = *(const float4*)(Ag + (long long)(bm + lrow + p*32)*K + lcol);

    for (int k0 = 0; k0 < K; k0 += 32){
        #pragma unroll
        for (int p = 0; p < 4; p++){
            int r = lrow + p*32;
            *(uint4*)&sA[r*LDT + lcol] =
                make_uint4(f2tf(pa[p].x), f2tf(pa[p].y), f2tf(pa[p].z), f2tf(pa[p].w));
            float4 vb = *(const float4*)(Bg + (long long)(bn + r)*K + k0 + lcol);
            *(uint4*)&sB[r*LDT + lcol] = make_uint4(f2tf(vb.x), f2tf(vb.y), f2tf(vb.z), f2tf(vb.w));
        }
        __syncthreads();
        if (k0 + 32 < K){
            #pragma unroll
            for (int p = 0; p < 4; p++)
                pa[p] = *(const float4*)(Ag + (long long)(bm + lrow + p*32)*K + k0 + 32 + lcol);
        }
        #pragma unroll
        for (int kk = 0; kk < 32; kk += 8){
            uint32_t af[4][4], bf[4][2];
            #pragma unroll
            for (int mi = 0; mi < 4; mi++){
                int r = wm + mi*16 + g;
                af[mi][0] = sA[ r    *LDT + kk + t    ];
                af[mi][1] = sA[(r+8) *LDT + kk + t    ];
                af[mi][2] = sA[ r    *LDT + kk + t + 4];
                af[mi][3] = sA[(r+8) *LDT + kk + t + 4];
            }
            #pragma unroll
            for (int ni = 0; ni < 4; ni++){
                int rn = wn + ni*8 + g;
                bf[ni][0] = sB[rn*LDT + kk + t    ];
                bf[ni][1] = sB[rn*LDT + kk + t + 4];
            }
            #pragma unroll
            for (int mi = 0; mi < 4; mi++)
                #pragma unroll
                for (int ni = 0; ni < 4; ni++)
                    mma_tf(acc[mi][ni], af[mi], bf[ni]);
        }
        __syncthreads();
    }

    #pragma unroll
    for (int mi = 0; mi < 4; mi++){
        int r0 = bm + wm + mi*16 + g;
        #pragma unroll
        for (int ni = 0; ni < 4; ni++){
            int c = bn + wn + ni*8 + 2*t;
            float* ac = acc[mi][ni];
            float b0 = bias[c], b1 = bias[c+1];
            *(float2*)(Cf + (long long)r0*N + c)     = make_float2(ac[0]+b0, ac[1]+b1);
            *(float2*)(Cf + (long long)(r0+8)*N + c) = make_float2(ac[2]+b0, ac[3]+b1);
        }
    }
}

// ---------------- bf16 m16n8k16 GEMM: CTA 128x256, warp tile 64x64 ----------
// 8 warps in 2(m) x 4(n) grid; 2-stage smem double buffer; occ 1 (reg-heavy).
// A: [M,K] bf16 rm, B: [N,K] bf16 rm. BK=64 bf16 (32 u32 cols, pitch LDT=36).
// Per iter: MMA(stage cur) -> STS(next stage from regs) -> LDG(t+2) -> sync.
// EPI 1: z selects (Wk,bk)->Cb or (Wq,bq)->Cb2   (K and Q in one launch)
// EPI 2: Cb = bf16(exp(acc/512)) + fused column-sum partials (E, z = batch)
#define BN2 256
#define ASZ_U (128*LDT)                        // A rows in a stage
#define STG_U ((128+BN2)*LDT)                  // u32 per stage (A+B) = 13824
#define GB_SMEM (2*STG_U*4 + 2*BN2*4)          // 110592 + 2048 = 112640 B

template<int EPI>
__global__ void __launch_bounds__(256, 1)
gemm_bf16(const __nv_bfloat16* __restrict__ Ag, const __nv_bfloat16* __restrict__ Bg,
          const __nv_bfloat16* __restrict__ Bg2,
          const float* __restrict__ bias, const float* __restrict__ bias2,
          __nv_bfloat16* __restrict__ Cb, __nv_bfloat16* __restrict__ Cb2,
          float* __restrict__ part,
          int M, int N, int K,
          long long strA, long long strB, long long strC)
{
    extern __shared__ __align__(16) uint32_t smx[];
    float* cpart = (float*)(smx + 2*STG_U);   // [2][BN2]

    const int tid  = threadIdx.x;
    const int z = blockIdx.z;
    const int bm = blockIdx.y*128, bn = blockIdx.x*BN2;
    const int lane = tid & 31, warp = tid >> 5;
    const int wm = (warp & 1)*64, wn = (warp >> 1)*64;   // 2x4 warp grid, 64x64
    const int g = lane >> 2, t = lane & 3;
    const int lrowA = tid >> 1;                // 0..127
    const int lchA  = (tid & 1)*4;             // 2 threads/A-row, 4 chunks each

    const __nv_bfloat16* Asel;
    const __nv_bfloat16* Bsel;
    if (EPI == 1){ Asel = Ag; Bsel = z ? Bg2 : Bg; }
    else         { Asel = Ag + (long long)z*strA; Bsel = Bg + (long long)z*strB; }

    const __nv_bfloat16* aptr = Asel + (long long)(bm + lrowA)*K + lchA*8;
    const __nv_bfloat16* bptr = Bsel + (long long)(bn + tid)*K;     // 1 thread/B-row
    const int sidxA = lrowA*LDT + lchA*4;
    const int sidxB = ASZ_U + tid*LDT;
    const int NT = K >> 6;                     // k-tiles of 64

    float acc[4][8][4];
    #pragma unroll
    for (int i = 0; i < 4; i++)
        #pragma unroll
        for (int j = 0; j < 8; j++)
            #pragma unroll
            for (int c = 0; c < 4; c++) acc[i][j][c] = 0.f;

    uint4 pa[4], pb[8];
    // tile 0 -> regs -> stage 0
    #pragma unroll
    for (int c = 0; c < 4; c++) pa[c] = *(const uint4*)(aptr + c*8);
    #pragma unroll
    for (int c = 0; c < 8; c++) pb[c] = *(const uint4*)(bptr + c*8);
    #pragma unroll
    for (int c = 0; c < 4; c++) *(uint4*)&smx[sidxA + c*4] = pa[c];
    #pragma unroll
    for (int c = 0; c < 8; c++) *(uint4*)&smx[sidxB + c*4] = pb[c];
    // tile 1 -> regs
    if (NT > 1){
        #pragma unroll
        for (int c = 0; c < 4; c++) pa[c] = *(const uint4*)(aptr + 64 + c*8);
        #pragma unroll
        for (int c = 0; c < 8; c++) pb[c] = *(const uint4*)(bptr + 64 + c*8);
    }
    __syncthreads();

    for (int it = 0; it < NT; it++){
        const uint32_t* sA = smx + (it & 1)*STG_U;
        const uint32_t* sB = sA + ASZ_U;
        #pragma unroll
        for (int kk = 0; kk < 32; kk += 8){    // each kk = one k16 step
            uint32_t af[4][4], bf[8][2];
            #pragma unroll
            for (int mi = 0; mi < 4; mi++){
                int r = wm + mi*16 + g;
                af[mi][0] = sA[ r    *LDT + kk + t    ];
                af[mi][1] = sA[(r+8) *LDT + kk + t    ];
                af[mi][2] = sA[ r    *LDT + kk + t + 4];
                af[mi][3] = sA[(r+8) *LDT + kk + t + 4];
            }
            #pragma unroll
            for (int ni = 0; ni < 8; ni++){
                int rn = wn + ni*8 + g;
                bf[ni][0] = sB[rn*LDT + kk + t    ];
                bf[ni][1] = sB[rn*LDT + kk + t + 4];
            }
            #pragma unroll
            for (int mi = 0; mi < 4; mi++)
                #pragma unroll
                for (int ni = 0; ni < 8; ni++)
                    mma_bf(acc[mi][ni], af[mi], bf[ni]);
        }
        if (it + 1 < NT){
            uint32_t* dA = smx + ((it + 1) & 1)*STG_U;
            #pragma unroll
            for (int c = 0; c < 4; c++) *(uint4*)&dA[sidxA + c*4] = pa[c];
            #pragma unroll
            for (int c = 0; c < 8; c++) *(uint4*)&dA[sidxB + c*4] = pb[c];
            if (it + 2 < NT){
                #pragma unroll
                for (int c = 0; c < 4; c++)
                    pa[c] = *(const uint4*)(aptr + (it + 2)*64 + c*8);
                #pragma unroll
                for (int c = 0; c < 8; c++)
                    pb[c] = *(const uint4*)(bptr + (it + 2)*64 + c*8);
            }
        }
        __syncthreads();
    }

    if (EPI == 1){
        const float*   bsel = z ? bias2 : bias;
        __nv_bfloat16* Co   = z ? Cb2   : Cb;
        #pragma unroll
        for (int mi = 0; mi < 4; mi++){
            int r0 = bm + wm + mi*16 + g;
            #pragma unroll
            for (int ni = 0; ni < 8; ni++){
                int c = bn + wn + ni*8 + 2*t;
                float* ac = acc[mi][ni];
                float b0 = bsel[c], b1 = bsel[c+1];
                *(__nv_bfloat162*)(Co + (long long)r0*N + c) =
                    __floats2bfloat162_rn(ac[0]+b0, ac[1]+b1);
                *(__nv_bfloat162*)(Co + (long long)(r0+8)*N + c) =
                    __floats2bfloat162_rn(ac[2]+b0, ac[3]+b1);
            }
        }
    } else {
        __nv_bfloat16* Co = Cb + (long long)z*strC;
        const float inv = 1.0f/512.0f;
        float csum[8][2];
        #pragma unroll
        for (int ni = 0; ni < 8; ni++){ csum[ni][0] = 0.f; csum[ni][1] = 0.f; }

        #pragma unroll
        for (int mi = 0; mi < 4; mi++){
            int r0 = bm + wm + mi*16 + g;
            #pragma unroll
            for (int ni = 0; ni < 8; ni++){
                int c = bn + wn + ni*8 + 2*t;
                float* ac = acc[mi][ni];
                float e0 = __expf(ac[0]*inv), e1 = __expf(ac[1]*inv);
                float e2 = __expf(ac[2]*inv), e3 = __expf(ac[3]*inv);
                *(__nv_bfloat162*)(Co + (long long)r0*N + c)     = __floats2bfloat162_rn(e0, e1);
                *(__nv_bfloat162*)(Co + (long long)(r0+8)*N + c) = __floats2bfloat162_rn(e2, e3);
                csum[ni][0] += e0 + e2;
                csum[ni][1] += e1 + e3;
            }
        }
        #pragma unroll
        for (int m = 4; m <= 16; m <<= 1)
            #pragma unroll
            for (int ni = 0; ni < 8; ni++){
                csum[ni][0] += __shfl_xor_sync(0xffffffffu, csum[ni][0], m);
                csum[ni][1] += __shfl_xor_sync(0xffffffffu, csum[ni][1], m);
            }
        if (lane < 4){   // g == 0; lane == t
            #pragma unroll
            for (int ni = 0; ni < 8; ni++){
                cpart[(warp & 1)*BN2 + wn + ni*8 + 2*lane    ] = csum[ni][0];
                cpart[(warp & 1)*BN2 + wn + ni*8 + 2*lane + 1] = csum[ni][1];
            }
        }
        __syncthreads();
        {
            float v = cpart[tid] + cpart[BN2 + tid];
            part[(((long long)z*32 + blockIdx.y)*(long long)S_) + bn + tid] = v;
        }
    }
}

// ---------------- Linv from 32 per-tile partials ----------------------------
__global__ void linv_kernel(const float* __restrict__ part, float* __restrict__ Linv){
    int i = blockIdx.x*256 + threadIdx.x;          // b*S + e
    int b = i >> 12, e = i & (S_-1);
    float s = 0.f;
    #pragma unroll
    for (int c = 0; c < 32; c++) s += part[(b*32 + c)*(long long)S_ + e];
    Linv[i] = 1.0f / s;
}

// ---------------- row-sum of E * Linv ---------------------------------------
__global__ void rowsum_kernel(const __nv_bfloat16* __restrict__ E,
                              const float* __restrict__ Linv, float* __restrict__ r){
    int s = blockIdx.x, b = blockIdx.y, tid = threadIdx.x;
    const __nv_bfloat162* row2 = (const __nv_bfloat162*)(E + ((long long)b*S_ + s)*S_);
    const float2* li2 = (const float2*)(Linv + b*S_);
    float acc = 0.f;
    #pragma unroll 4
    for (int i = tid; i < S_/2; i += 256){
        float2 v = __bfloat1622float2(row2[i]);
        float2 l = li2[i];
        acc += v.x*l.x + v.y*l.y;
    }
    __shared__ float red[256];
    red[tid] = acc; __syncthreads();
    for (int st = 128; st > 0; st >>= 1){
        if (tid < st) red[tid] += red[tid + st];
        __syncthreads();
    }
    if (tid == 0) r[(long long)b*S_ + s] = red[0];
}

// ---------------- out = tanh(r * VL + bl) -----------------------------------
__global__ void out_kernel(const float* __restrict__ VL, const float* __restrict__ r,
                           const float* __restrict__ bl, float* __restrict__ out){
    long long i = (long long)blockIdx.x*256 + threadIdx.x;
    float4 v = ((const float4*)VL)[i];
    float rv = r[i >> 7];
    float4 b4 = ((const float4*)bl)[(int)(i & 127)];
    float4 o;
    o.x = tanhf(rv*v.x + b4.x);
    o.y = tanhf(rv*v.y + b4.y);
    o.z = tanhf(rv*v.z + b4.z);
    o.w = tanhf(rv*v.w + b4.w);
    ((float4*)out)[i] = o;
}

// ---------------- launcher --------------------------------------------------
extern "C" void kernel_launch(void* const* d_in, const int* in_sizes, int n_in,
                              void* d_out, int out_size){
    const float* xs = (const float*)d_in[0];
    const float* Wk = (const float*)d_in[1];
    const float* bk = (const float*)d_in[2];
    const float* Wq = (const float*)d_in[3];
    const float* bq = (const float*)d_in[4];
    const float* Wv = (const float*)d_in[5];
    const float* bv = (const float*)d_in[6];
    const float* Wl = (const float*)d_in[7];
    const float* bl = (const float*)d_in[8];
    float* out = (float*)d_out;
    (void)in_sizes; (void)n_in; (void)out_size;

    float *pVL, *pPart, *pLinv, *pR, *pWcP, *pWc, *pBc;
    __nv_bfloat16 *pXh, *pWkh, *pWqh, *pKh, *pQh, *pE;
    cudaGetSymbolAddress((void**)&pXh,   g_Xh);
    cudaGetSymbolAddress((void**)&pWkh,  g_Wkh);
    cudaGetSymbolAddress((void**)&pWqh,  g_Wqh);
    cudaGetSymbolAddress((void**)&pKh,   g_Kh);
    cudaGetSymbolAddress((void**)&pQh,   g_Qh);
    cudaGetSymbolAddress((void**)&pVL,   g_VL);
    cudaGetSymbolAddress((void**)&pE,    g_E);
    cudaGetSymbolAddress((void**)&pPart, g_part);
    cudaGetSymbolAddress((void**)&pLinv, g_Linv);
    cudaGetSymbolAddress((void**)&pR,    g_r);
    cudaGetSymbolAddress((void**)&pWcP,  g_WcP);
    cudaGetSymbolAddress((void**)&pWc,   g_Wc);
    cudaGetSymbolAddress((void**)&pBc,   g_bc);

    static bool attr_done = false;
    if (!attr_done){
        cudaFuncSetAttribute(gemm_bf16<1>, cudaFuncAttributeMaxDynamicSharedMemorySize, GB_SMEM);
        cudaFuncSetAttribute(gemm_bf16<2>, cudaFuncAttributeMaxDynamicSharedMemorySize, GB_SMEM);
        attr_done = true;
    }

    // 0) bf16 casts
    cvt_bf16<<<(M1*D_/8)/256, 256>>>((const float4*)xs, (uint4*)pXh);
    cvt_bf16<<<(D_*D_/8)/256, 256>>>((const float4*)Wk, (uint4*)pWkh);
    cvt_bf16<<<(D_*D_/8)/256, 256>>>((const float4*)Wq, (uint4*)pWqh);

    // 1) combined last-layer weights: Wc = Wl@Wv (split-K2), bc = Wl@bv
    wc_gemm<<<dim3(D_/64, D_/64, 2), 256>>>(Wl, Wv, pWcP);
    wc_reduce<<<(D_*D_/4)/256, 256>>>((const float4*)pWcP, (float4*)pWc);
    bc_kernel<<<D_, 128>>>(Wl, bv, pBc);

    // 2) K and Q fused in one bf16 HMMA launch (z selects weight/bias/output)
    gemm_bf16<1><<<dim3(D_/BN2, M1/128, 2), 256, GB_SMEM>>>(
        pXh, pWkh, pWqh, bk, bq, pKh, pQh, nullptr, M1, D_, D_, 0, 0, 0);

    // 3) VL in tf32 (accuracy-critical output path, A-prefetched)
    gemm_tf32<<<dim3(D_/BNT, M1/BMT), 256>>>(xs, pWc, pBc, pVL, M1, D_, D_);

    // 4) E[b] = exp((K@Q^T)/512), fused column-sum partials
    gemm_bf16<2><<<dim3(S_/BN2, S_/128, B_), 256, GB_SMEM>>>(
        pKh, pQh, nullptr, nullptr, nullptr, pE, nullptr, pPart,
        S_, S_, D_, (long long)S_*D_, (long long)S_*D_, (long long)S_*S_);

    // 5) Linv, r
    linv_kernel<<<(B_*S_)/256, 256>>>(pPart, pLinv);
    rowsum_kernel<<<dim3(S_, B_), 256>>>(pE, pLinv, pR);

    // 6) out = tanh(r * VL + bl)
    out_kernel<<<(B_*S_*D_/4)/256, 256>>>(pVL, pR, bl, out);
}